// round 13
// baseline (speedup 1.0000x reference)
#include <cuda_runtime.h>

// DAM softmax loss — persistent block-per-row, rolling load pipeline,
// inline target-margin correction. R12 structure, grid fixed for GB300's
// 152 SMs (was sized for B300's 148 -> 32 SMs ran under-subscribed).
//   logits = S*costh, except target col: S*(ct - 0.15*exp(1-ct))
//   loss = mean_row( logsumexp(logits_row) - logits_row[target] )
// costh in [0,1) -> S*costh < 15 -> fixed max 15, single pass.

static constexpr int   B_ROWS  = 8192;
static constexpr int   C_COLS  = 10000;
static constexpr int   THREADS = 256;
static constexpr int   NUM_SMS = 152;                       // GB300 (not 148!)
static constexpr int   BLOCKS_PER_SM = 8;
static constexpr int   GRID    = NUM_SMS * BLOCKS_PER_SM;   // 1216, one wave
static constexpr int   NVEC    = C_COLS / 4;                // 2500
static constexpr int   ROUNDS  = (NVEC + THREADS - 1) / THREADS;  // 10
static constexpr int   DEPTH   = 4;                         // pipeline depth
static constexpr float S_SCALE = 15.0f;
static constexpr float MARGIN_OVER_LAMDA = 0.3f / 2.0f;     // 0.15

__device__ double       g_acc  = 0.0;
__device__ unsigned int g_done = 0u;

__device__ __forceinline__ float ex2_approx(float x) {
    float r;
    asm("ex2.approx.f32 %0, %1;" : "=f"(r) : "f"(x));
    return r;
}

// Streaming 128-bit load, evict-first, with 256B L2 prefetch hint.
__device__ __forceinline__ float4 ldcs256(const float4* p) {
    float4 v;
    asm("ld.global.nc.cs.L2::256B.v4.f32 {%0,%1,%2,%3}, [%4];"
        : "=f"(v.x), "=f"(v.y), "=f"(v.z), "=f"(v.w) : "l"(p));
    return v;
}

// Sentinel: drives ex2 argument hugely negative -> contributes exactly 0.
__device__ __forceinline__ float4 sentinel4() {
    return make_float4(-1.0e4f, -1.0e4f, -1.0e4f, -1.0e4f);
}

__global__ void __launch_bounds__(THREADS, BLOCKS_PER_SM)
dam_loss_pipe_kernel(const float* __restrict__ costh,
                     const int* __restrict__ label,
                     float* __restrict__ out) {
    const int tid = threadIdx.x;

    // exp(S*c - 15) = exp2( (S*log2e)*c - 15*log2e )
    const float L2E  = 1.4426950408889634f;
    const float SL2E = S_SCALE * L2E;
    const float BIAS = -S_SCALE * L2E;

    __shared__ float warp_sums[2][THREADS / 32];
    __shared__ float sh_ct2[2];

    int parity = 0;
    for (int row = blockIdx.x; row < B_ROWS; row += GRID, parity ^= 1) {
        const float4* __restrict__ rp =
            reinterpret_cast<const float4*>(costh + (size_t)row * C_COLS);

        // Target column info (same address for all threads -> broadcast hit).
        int t = __ldg(&label[row]);
        t = min(max(t, 0), C_COLS - 1);
        const int tv = t >> 2;   // which float4
        const int tc = t & 3;    // which component

        // Depth-4 rolling pipeline over 10 rounds.
        // Round r consumes idx = tid + r*256 (loaded DEPTH rounds earlier).
        float4 b0 = ldcs256(&rp[tid]);                 // rounds 0..3: in range
        float4 b1 = ldcs256(&rp[tid + THREADS]);
        float4 b2 = ldcs256(&rp[tid + 2 * THREADS]);
        float4 b3 = ldcs256(&rp[tid + 3 * THREADS]);

        float s0 = 0.0f, s1 = 0.0f, s2 = 0.0f, s3 = 0.0f;

        #pragma unroll
        for (int r = 0; r < ROUNDS; r++) {
            float4 cur = b0;
            b0 = b1; b1 = b2; b2 = b3;
            // Prefetch for consumption round r+DEPTH (last valid: ROUNDS-1).
            if (r + DEPTH < ROUNDS) {
                const int pidx = tid + (r + DEPTH) * THREADS;
                // Only the final prefetch round (pidx up to 2559) is partial.
                b3 = (pidx < NVEC) ? ldcs256(&rp[pidx]) : sentinel4();
            } else {
                b3 = sentinel4();
            }

            const int idx = tid + r * THREADS;
            if (idx == tv) {       // exactly one thread, one round, per row
                float ct = (tc == 0) ? cur.x : (tc == 1) ? cur.y
                          : (tc == 2) ? cur.z : cur.w;
                float ct2 = ct - MARGIN_OVER_LAMDA * expf(1.0f - ct);
                if (tc == 0) cur.x = ct2;
                else if (tc == 1) cur.y = ct2;
                else if (tc == 2) cur.z = ct2;
                else cur.w = ct2;
                sh_ct2[parity] = ct2;
            }

            s0 += ex2_approx(fmaf(cur.x, SL2E, BIAS));
            s1 += ex2_approx(fmaf(cur.y, SL2E, BIAS));
            s2 += ex2_approx(fmaf(cur.z, SL2E, BIAS));
            s3 += ex2_approx(fmaf(cur.w, SL2E, BIAS));
        }

        float s = (s0 + s1) + (s2 + s3);
        #pragma unroll
        for (int off = 16; off; off >>= 1)
            s += __shfl_xor_sync(0xffffffffu, s, off);

        if ((tid & 31) == 0) warp_sums[parity][tid >> 5] = s;
        __syncthreads();

        if (tid == 0) {
            float tot = 0.0f;
            #pragma unroll
            for (int w = 0; w < THREADS / 32; w++) tot += warp_sums[parity][w];
            const float ct2 = sh_ct2[parity];
            // tot already contains the corrected target term.
            const float loss_row = 15.0f + logf(tot) - S_SCALE * ct2;
            atomicAdd(&g_acc, (double)loss_row);   // result unused -> RED
        }
        // Parity double-buffering: next row uses the other buffers, and
        // thread 0 must pass the next row's __syncthreads before any buffer
        // with this parity is written again.
    }

    if (tid == 0) {
        __threadfence();
        const unsigned ticket = atomicAdd(&g_done, 1u);
        if (ticket == (unsigned)(GRID - 1)) {
            out[0] = (float)(g_acc * (1.0 / (double)B_ROWS));
            g_acc  = 0.0;
            g_done = 0u;
            __threadfence();
        }
    }
}

extern "C" void kernel_launch(void* const* d_in, const int* in_sizes, int n_in,
                              void* d_out, int out_size) {
    const float* costh = (const float*)d_in[0];
    const int*   label = (const int*)d_in[1];
    float*       out   = (float*)d_out;

    dam_loss_pipe_kernel<<<GRID, THREADS>>>(costh, label, out);
}